// round 8
// baseline (speedup 1.0000x reference)
#include <cuda_runtime.h>
#include <math.h>
#include <stdint.h>

#define HID    512
#define BATCH  4096
#define TSTEPS 20

#define BM 64
#define BN 64
#define BKB 64                          // K bytes per chunk (int8)
#define SKB 80                          // padded smem row stride in BYTES (conflict-free)
#define TILE_B (64 * SKB)               // 5120 B per 64x64 int8 tile
#define F_STAGE_B (4 * TILE_B)          // A + Wi + Wg + Wo
#define F_SMEM (3 * F_STAGE_B)          // 61440 B
#define W_STAGE_B (2 * TILE_B)
#define W_SMEM (3 * W_STAGE_B)          // 30720 B

// quantization scales
#define WSCALE  2873.0f                 // 127 / (1/sqrt(512))
#define ZSCALE  15.875f                 // 127 / 8  (|z| < 8 guaranteed)
#define DHSCALE 127.0f                  // |dh| < 1
#define DQF (1.0f / (ZSCALE * WSCALE))  // fused dequant
#define DQW (1.0f / (DHSCALE * WSCALE)) // wout dequant

// ---------------- scratch ----------------------------------------------------
__device__ __align__(16) float   g_z  [BATCH * HID];
__device__ __align__(16) int8_t  g_zi [BATCH * HID];
__device__ __align__(16) int8_t  g_dhi[BATCH * HID];
__device__ __align__(16) float   g_s  [BATCH * HID];
__device__ __align__(16) int8_t  g_wi [4][HID * HID];   // Wi, Wg, Wo, Wout (int8)

// ---------------- helpers ----------------------------------------------------
static __device__ __forceinline__ uint32_t smem_u32(const void* p) {
    uint32_t a;
    asm("{ .reg .u64 t; cvta.to.shared.u64 t, %1; cvt.u32.u64 %0, t; }" : "=r"(a) : "l"(p));
    return a;
}
#define CP16(dst, src) \
    asm volatile("cp.async.cg.shared.global [%0], [%1], 16;" :: "r"(dst), "l"(src))
#define CPC()  asm volatile("cp.async.commit_group;" ::: "memory")
#define CPW1() asm volatile("cp.async.wait_group 1;" ::: "memory")
#define CPW0() asm volatile("cp.async.wait_group 0;" ::: "memory")

__device__ __forceinline__ void ldm4(uint32_t a, uint32_t& r0, uint32_t& r1,
                                     uint32_t& r2, uint32_t& r3) {
    asm volatile("ldmatrix.sync.aligned.m8n8.x4.shared.b16 {%0,%1,%2,%3}, [%4];"
                 : "=r"(r0), "=r"(r1), "=r"(r2), "=r"(r3) : "r"(a));
}
__device__ __forceinline__ void mma_s8(int* c, const uint32_t* a, uint32_t b0, uint32_t b1) {
    asm volatile("mma.sync.aligned.m16n8k32.row.col.s32.s8.s8.s32 "
                 "{%0,%1,%2,%3},{%4,%5,%6,%7},{%8,%9},{%0,%1,%2,%3};"
                 : "+r"(c[0]), "+r"(c[1]), "+r"(c[2]), "+r"(c[3])
                 : "r"(a[0]), "r"(a[1]), "r"(a[2]), "r"(a[3]), "r"(b0), "r"(b1));
}
__device__ __forceinline__ float fsig(float x)  { return __fdividef(1.f, 1.f + __expf(-x)); }
__device__ __forceinline__ float ftanh(float x) { return __fdividef(2.f, 1.f + __expf(-2.f * x)) - 1.f; }
__device__ __forceinline__ int8_t q8(float v, float s) {
    int x = __float2int_rn(v * s);
    x = max(-127, min(127, x));
    return (int8_t)x;
}

// ---------------- setup ------------------------------------------------------
__global__ void w2i8_kernel(const float* __restrict__ Wi, const float* __restrict__ Wg,
                            const float* __restrict__ Wo, const float* __restrict__ Wout) {
    int i = blockIdx.x * blockDim.x + threadIdx.x;
    if (i >= 4 * HID * HID) return;
    int m = i >> 18, r = i & (HID * HID - 1);
    const float* src = (m == 0) ? Wi : (m == 1) ? Wg : (m == 2) ? Wo : Wout;
    g_wi[m][r] = q8(src[r], WSCALE);
}

__global__ void copy_z_kernel(const float* __restrict__ y) {
    int i = blockIdx.x * blockDim.x + threadIdx.x;
    if (i < BATCH * HID) { float v = y[i]; g_z[i] = v; g_zi[i] = q8(v, ZSCALE); }
}

// ---------------- cp.async issuers (stage 0..2) ------------------------------
__device__ __forceinline__ void f_issue(uint32_t sb, int tid, int bm, int bn, int ch, int stage) {
    const uint32_t base = sb + (uint32_t)stage * F_STAGE_B;
    const int k0 = ch * BKB;
    #pragma unroll
    for (int i = 0; i < 4; ++i) {
        int idx = i * 256 + tid;              // 0..1023 segments of 16B
        int tl = idx >> 8, r = (idx >> 2) & 63, c = idx & 3;
        const int8_t* src = (tl == 0)
            ? (g_zi + (bm + r) * HID + k0 + c * 16)
            : (g_wi[tl - 1] + (bn + r) * HID + k0 + c * 16);
        uint32_t dst = base + (uint32_t)(tl * TILE_B + r * SKB + c * 16);
        CP16(dst, src);
    }
    CPC();
}
__device__ __forceinline__ void w_issue(uint32_t sb, int tid, int bm, int bn, int ch, int stage) {
    const uint32_t base = sb + (uint32_t)stage * W_STAGE_B;
    const int k0 = ch * BKB;
    #pragma unroll
    for (int i = 0; i < 2; ++i) {
        int idx = i * 256 + tid;              // 0..511
        int tl = idx >> 8, r = (idx >> 2) & 63, c = idx & 3;
        const int8_t* src = (tl == 0)
            ? (g_dhi + (bm + r) * HID + k0 + c * 16)
            : (g_wi[3] + (bn + r) * HID + k0 + c * 16);
        uint32_t dst = base + (uint32_t)(tl * TILE_B + r * SKB + c * 16);
        CP16(dst, src);
    }
    CPC();
}

// ---------------- fused i/g/o int8 MMA GEMM (64x64 tile, 8 warps, occ 2) -----
// dh = sig(z@Wo^T) * tanh( sig(z@Wi^T) * tanh(z@Wg^T) ) -> g_dhi (int8)
__global__ __launch_bounds__(256, 2) void fused_igo_mma() {
    extern __shared__ int8_t sm[];
    const uint32_t sb = smem_u32(sm);
    const int tid = threadIdx.x, lane = tid & 31, wid = tid >> 5;
    const int warpM = wid & 1, warpN = wid >> 1;      // 2 x 4 warps, warp tile 32x16
    const int bm = blockIdx.x * BM, bn = blockIdx.y * BN;

    int acc[3][2][2][4];                              // [weight][mi][ni][4] s32
    #pragma unroll
    for (int w = 0; w < 3; ++w)
        #pragma unroll
        for (int mi = 0; mi < 2; ++mi)
            #pragma unroll
            for (int ni = 0; ni < 2; ++ni)
                #pragma unroll
                for (int q = 0; q < 4; ++q) acc[w][mi][ni][q] = 0;

    // byte-unit ldmatrix addressing (b16 view of int8 data)
    const int am = warpM * 32 + (lane & 15);
    const int ak = (lane >> 4) << 4;                  // 0 or 16 bytes
    const int bnrow = warpN * 16 + ((lane >> 4) << 3) + (lane & 7);
    const int bk = ((lane >> 3) & 1) << 4;            // 0 or 16 bytes

    f_issue(sb, tid, bm, bn, 0, 0);
    f_issue(sb, tid, bm, bn, 1, 1);

    int stage = 0;
    #pragma unroll 1
    for (int ch = 0; ch < HID / BKB; ++ch) {
        if (ch < HID / BKB - 1) { CPW1(); } else { CPW0(); }
        __syncthreads();
        if (ch + 2 < HID / BKB) {
            int ns = stage + 2; if (ns >= 3) ns -= 3;
            f_issue(sb, tid, bm, bn, ch + 2, ns);
        }
        const uint32_t base = sb + (uint32_t)stage * F_STAGE_B;
        #pragma unroll
        for (int ks = 0; ks < BKB; ks += 32) {        // 2 slices of k=32
            uint32_t fa[2][4];
            uint32_t aadr = base + (uint32_t)(am * SKB + ks + ak);
            ldm4(aadr,            fa[0][0], fa[0][1], fa[0][2], fa[0][3]);
            ldm4(aadr + 16 * SKB, fa[1][0], fa[1][1], fa[1][2], fa[1][3]);
            const uint32_t boff = (uint32_t)(bnrow * SKB + ks + bk);
            #pragma unroll
            for (int w = 0; w < 3; ++w) {
                uint32_t b0, b1, b2, b3;
                ldm4(base + (uint32_t)((w + 1) * TILE_B) + boff, b0, b1, b2, b3);
                mma_s8(acc[w][0][0], fa[0], b0, b1);
                mma_s8(acc[w][0][1], fa[0], b2, b3);
                mma_s8(acc[w][1][0], fa[1], b0, b1);
                mma_s8(acc[w][1][1], fa[1], b2, b3);
            }
        }
        if (++stage >= 3) stage -= 3;
    }

    // epilogue: dequant + dh activation -> g_dhi (int8)
    #pragma unroll
    for (int mi = 0; mi < 2; ++mi) {
        const int r = bm + warpM * 32 + mi * 16 + (lane >> 2);
        #pragma unroll
        for (int ni = 0; ni < 2; ++ni) {
            const int col = bn + warpN * 16 + ni * 8 + ((lane & 3) << 1);
            float pi0 = acc[0][mi][ni][0] * DQF, pg0 = acc[1][mi][ni][0] * DQF, po0 = acc[2][mi][ni][0] * DQF;
            float pi1 = acc[0][mi][ni][1] * DQF, pg1 = acc[1][mi][ni][1] * DQF, po1 = acc[2][mi][ni][1] * DQF;
            float pi2 = acc[0][mi][ni][2] * DQF, pg2 = acc[1][mi][ni][2] * DQF, po2 = acc[2][mi][ni][2] * DQF;
            float pi3 = acc[0][mi][ni][3] * DQF, pg3 = acc[1][mi][ni][3] * DQF, po3 = acc[2][mi][ni][3] * DQF;
            float d0 = fsig(po0) * ftanh(fsig(pi0) * ftanh(pg0));
            float d1 = fsig(po1) * ftanh(fsig(pi1) * ftanh(pg1));
            float d2 = fsig(po2) * ftanh(fsig(pi2) * ftanh(pg2));
            float d3 = fsig(po3) * ftanh(fsig(pi3) * ftanh(pg3));
            char2 lo; lo.x = q8(d0, DHSCALE); lo.y = q8(d1, DHSCALE);
            char2 hi; hi.x = q8(d2, DHSCALE); hi.y = q8(d3, DHSCALE);
            *(char2*)(g_dhi + r * HID + col)       = lo;
            *(char2*)(g_dhi + (r + 8) * HID + col) = hi;
        }
    }
}

// ---------------- Wout int8 GEMM: s = dh @ Wout^T + bout ---------------------
__global__ __launch_bounds__(256, 3) void wout_mma(const float* __restrict__ bout) {
    extern __shared__ int8_t sm[];
    const uint32_t sb = smem_u32(sm);
    const int tid = threadIdx.x, lane = tid & 31, wid = tid >> 5;
    const int warpM = wid & 1, warpN = wid >> 1;
    const int bm = blockIdx.x * BM, bn = blockIdx.y * BN;

    int acc[2][2][4];
    #pragma unroll
    for (int mi = 0; mi < 2; ++mi)
        #pragma unroll
        for (int ni = 0; ni < 2; ++ni)
            #pragma unroll
            for (int q = 0; q < 4; ++q) acc[mi][ni][q] = 0;

    const int am = warpM * 32 + (lane & 15);
    const int ak = (lane >> 4) << 4;
    const int bnrow = warpN * 16 + ((lane >> 4) << 3) + (lane & 7);
    const int bk = ((lane >> 3) & 1) << 4;

    w_issue(sb, tid, bm, bn, 0, 0);
    w_issue(sb, tid, bm, bn, 1, 1);

    int stage = 0;
    #pragma unroll 1
    for (int ch = 0; ch < HID / BKB; ++ch) {
        if (ch < HID / BKB - 1) { CPW1(); } else { CPW0(); }
        __syncthreads();
        if (ch + 2 < HID / BKB) {
            int ns = stage + 2; if (ns >= 3) ns -= 3;
            w_issue(sb, tid, bm, bn, ch + 2, ns);
        }
        const uint32_t base = sb + (uint32_t)stage * W_STAGE_B;
        #pragma unroll
        for (int ks = 0; ks < BKB; ks += 32) {
            uint32_t fa[2][4], b0, b1, b2, b3;
            uint32_t aadr = base + (uint32_t)(am * SKB + ks + ak);
            ldm4(aadr,            fa[0][0], fa[0][1], fa[0][2], fa[0][3]);
            ldm4(aadr + 16 * SKB, fa[1][0], fa[1][1], fa[1][2], fa[1][3]);
            ldm4(base + (uint32_t)TILE_B + (uint32_t)(bnrow * SKB + ks + bk), b0, b1, b2, b3);
            mma_s8(acc[0][0], fa[0], b0, b1);
            mma_s8(acc[0][1], fa[0], b2, b3);
            mma_s8(acc[1][0], fa[1], b0, b1);
            mma_s8(acc[1][1], fa[1], b2, b3);
        }
        if (++stage >= 3) stage -= 3;
    }

    #pragma unroll
    for (int mi = 0; mi < 2; ++mi) {
        const int r = bm + warpM * 32 + mi * 16 + (lane >> 2);
        #pragma unroll
        for (int ni = 0; ni < 2; ++ni) {
            const int col = bn + warpN * 16 + ni * 8 + ((lane & 3) << 1);
            float b0v = bout[col], b1v = bout[col + 1];
            float2 lo = { acc[mi][ni][0] * DQW + b0v, acc[mi][ni][1] * DQW + b1v };
            float2 hi = { acc[mi][ni][2] * DQW + b0v, acc[mi][ni][3] * DQW + b1v };
            *(float2*)(g_s + r * HID + col)       = lo;
            *(float2*)(g_s + (r + 8) * HID + col) = hi;
        }
    }
}

// ---------------- fused softmax(s)->z update + softmax(z)->out[t+1] ----------
__global__ __launch_bounds__(256) void update_out_kernel(
    const float* __restrict__ ts, const float* __restrict__ Wfc,
    const float* __restrict__ bfc, float* __restrict__ out, int t)
{
    const int b = blockIdx.x;
    const int tid = threadIdx.x;
    __shared__ float red_a[8], red_b[8];

    float v0 = g_s[b * HID + tid], v1 = g_s[b * HID + tid + 256];
    float m = fmaxf(v0, v1);
    #pragma unroll
    for (int o = 16; o; o >>= 1) m = fmaxf(m, __shfl_xor_sync(0xffffffffu, m, o));
    if ((tid & 31) == 0) red_a[tid >> 5] = m;
    __syncthreads();
    if (tid == 0) {
        float mm = red_a[0];
        #pragma unroll
        for (int i = 1; i < 8; ++i) mm = fmaxf(mm, red_a[i]);
        red_a[0] = mm;
    }
    __syncthreads();
    m = red_a[0];
    __syncthreads();
    float e0 = __expf(v0 - m), e1 = __expf(v1 - m);
    float s = e0 + e1;
    #pragma unroll
    for (int o = 16; o; o >>= 1) s += __shfl_xor_sync(0xffffffffu, s, o);
    if ((tid & 31) == 0) red_a[tid >> 5] = s;
    __syncthreads();
    if (tid == 0) {
        float ss = 0.f;
        #pragma unroll
        for (int i = 0; i < 8; ++i) ss += red_a[i];
        red_a[0] = ss;
    }
    __syncthreads();
    float dt = ts[t + 1] - ts[t];
    float inv = __fdividef(dt, red_a[0]);
    float z0 = g_z[b * HID + tid      ] + e0 * inv;
    float z1 = g_z[b * HID + tid + 256] + e1 * inv;
    g_z[b * HID + tid      ] = z0;
    g_z[b * HID + tid + 256] = z1;
    g_zi[b * HID + tid      ] = q8(z0, ZSCALE);
    g_zi[b * HID + tid + 256] = q8(z1, ZSCALE);
    __syncthreads();

    m = fmaxf(z0, z1);
    #pragma unroll
    for (int o = 16; o; o >>= 1) m = fmaxf(m, __shfl_xor_sync(0xffffffffu, m, o));
    if ((tid & 31) == 0) red_a[tid >> 5] = m;
    __syncthreads();
    if (tid == 0) {
        float mm = red_a[0];
        #pragma unroll
        for (int i = 1; i < 8; ++i) mm = fmaxf(mm, red_a[i]);
        red_a[0] = mm;
    }
    __syncthreads();
    m = red_a[0];
    __syncthreads();
    e0 = __expf(z0 - m); e1 = __expf(z1 - m);
    s = e0 + e1;
    float d = e0 * Wfc[tid] + e1 * Wfc[tid + 256];
    #pragma unroll
    for (int o = 16; o; o >>= 1) {
        s += __shfl_xor_sync(0xffffffffu, s, o);
        d += __shfl_xor_sync(0xffffffffu, d, o);
    }
    if ((tid & 31) == 0) { red_a[tid >> 5] = s; red_b[tid >> 5] = d; }
    __syncthreads();
    if (tid == 0) {
        float ss = 0.f, dd = 0.f;
        #pragma unroll
        for (int i = 0; i < 8; ++i) { ss += red_a[i]; dd += red_b[i]; }
        out[b * TSTEPS + t + 1] = __fdividef(dd, ss) + bfc[0];
    }
}

// out[b, 0] = softmax_row(z[b]) . Wfc + bfc
__global__ __launch_bounds__(256) void softmaxdot_kernel(
    const float* __restrict__ Wfc, const float* __restrict__ bfc,
    float* __restrict__ out)
{
    const int b = blockIdx.x;
    const int tid = threadIdx.x;
    float v0 = g_z[b * HID + tid], v1 = g_z[b * HID + tid + 256];
    __shared__ float red_s[8], red_d[8];

    float m = fmaxf(v0, v1);
    #pragma unroll
    for (int o = 16; o; o >>= 1) m = fmaxf(m, __shfl_xor_sync(0xffffffffu, m, o));
    if ((tid & 31) == 0) red_s[tid >> 5] = m;
    __syncthreads();
    if (tid == 0) {
        float mm = red_s[0];
        #pragma unroll
        for (int i = 1; i < 8; ++i) mm = fmaxf(mm, red_s[i]);
        red_s[0] = mm;
    }
    __syncthreads();
    m = red_s[0];
    __syncthreads();
    float e0 = __expf(v0 - m), e1 = __expf(v1 - m);
    float s = e0 + e1;
    float d = e0 * Wfc[tid] + e1 * Wfc[tid + 256];
    #pragma unroll
    for (int o = 16; o; o >>= 1) {
        s += __shfl_xor_sync(0xffffffffu, s, o);
        d += __shfl_xor_sync(0xffffffffu, d, o);
    }
    if ((tid & 31) == 0) { red_s[tid >> 5] = s; red_d[tid >> 5] = d; }
    __syncthreads();
    if (tid == 0) {
        float ss = 0.f, dd = 0.f;
        #pragma unroll
        for (int i = 0; i < 8; ++i) { ss += red_s[i]; dd += red_d[i]; }
        out[b * TSTEPS + 0] = __fdividef(dd, ss) + bfc[0];
    }
}

// ---------------- launch -----------------------------------------------------
extern "C" void kernel_launch(void* const* d_in, const int* in_sizes, int n_in,
                              void* d_out, int out_size) {
    const float* y    = (const float*)d_in[0];
    const float* ts   = (const float*)d_in[1];
    const float* Wi   = (const float*)d_in[2];
    // d_in[3] = Wf — dead in the reference (f computed but unused), skipped.
    const float* Wg   = (const float*)d_in[4];
    const float* Wo   = (const float*)d_in[5];
    const float* Wout = (const float*)d_in[6];
    const float* bout = (const float*)d_in[7];
    const float* Wfc  = (const float*)d_in[8];
    const float* bfc  = (const float*)d_in[9];
    float* out = (float*)d_out;

    cudaFuncSetAttribute(fused_igo_mma, cudaFuncAttributeMaxDynamicSharedMemorySize, F_SMEM);
    cudaFuncSetAttribute(wout_mma,      cudaFuncAttributeMaxDynamicSharedMemorySize, W_SMEM);

    w2i8_kernel<<<(4 * HID * HID + 255) / 256, 256>>>(Wi, Wg, Wo, Wout);
    copy_z_kernel<<<(BATCH * HID + 255) / 256, 256>>>(y);
    softmaxdot_kernel<<<BATCH, 256>>>(Wfc, bfc, out);

    dim3 ggrid(BATCH / BM, HID / BN);   // 64 x 8
    for (int t = 0; t < TSTEPS - 1; ++t) {
        fused_igo_mma<<<ggrid, 256, F_SMEM>>>();
        wout_mma<<<ggrid, 256, W_SMEM>>>(bout);
        update_out_kernel<<<BATCH, 256>>>(ts, Wfc, bfc, out, t);
    }
}

// round 9
// speedup vs baseline: 1.9128x; 1.9128x over previous
#include <cuda_runtime.h>
#include <cuda_fp16.h>
#include <math.h>
#include <stdint.h>

#define HID    512
#define BATCH  4096
#define TSTEPS 20

#define BM 128
#define BN 128
#define BKE 64                          // K elements per chunk
#define SKB 144                         // padded smem row stride in BYTES (64 fp16 = 128B + 16)
#define TILE_B (128 * SKB)              // 18432 B per 128x64-fp16 tile
#define F_STAGE_B (4 * TILE_B)          // A + Wi + Wg + Wo = 73728
#define F_SMEM (3 * F_STAGE_B)          // 221184 B (3-stage)
#define W_STAGE_B (2 * TILE_B)          // 36864
#define W_SMEM (3 * W_STAGE_B)          // 110592 B (3-stage)

// ---------------- scratch ----------------------------------------------------
__device__ __align__(16) float   g_z  [BATCH * HID];
__device__ __align__(16) __half  g_zh [BATCH * HID];
__device__ __align__(16) __half  g_dhh[BATCH * HID];
__device__ __align__(16) float   g_s  [BATCH * HID];
__device__ __align__(16) __half  g_wh [4][HID * HID];   // Wi, Wg, Wo, Wout (fp16)

// ---------------- helpers ----------------------------------------------------
static __device__ __forceinline__ uint32_t smem_u32(const void* p) {
    uint32_t a;
    asm("{ .reg .u64 t; cvta.to.shared.u64 t, %1; cvt.u32.u64 %0, t; }" : "=r"(a) : "l"(p));
    return a;
}
#define CP16(dst, src) \
    asm volatile("cp.async.cg.shared.global [%0], [%1], 16;" :: "r"(dst), "l"(src))
#define CPC()  asm volatile("cp.async.commit_group;" ::: "memory")
#define CPW1() asm volatile("cp.async.wait_group 1;" ::: "memory")
#define CPW0() asm volatile("cp.async.wait_group 0;" ::: "memory")

__device__ __forceinline__ void ldm4(uint32_t a, uint32_t& r0, uint32_t& r1,
                                     uint32_t& r2, uint32_t& r3) {
    asm volatile("ldmatrix.sync.aligned.m8n8.x4.shared.b16 {%0,%1,%2,%3}, [%4];"
                 : "=r"(r0), "=r"(r1), "=r"(r2), "=r"(r3) : "r"(a));
}
// f16 accumulate: C/D are 2 regs (half2 x2)
__device__ __forceinline__ void mma_f16(uint32_t* c, const uint32_t* a, uint32_t b0, uint32_t b1) {
    asm volatile("mma.sync.aligned.m16n8k16.row.col.f16.f16.f16.f16 "
                 "{%0,%1},{%2,%3,%4,%5},{%6,%7},{%0,%1};"
                 : "+r"(c[0]), "+r"(c[1])
                 : "r"(a[0]), "r"(a[1]), "r"(a[2]), "r"(a[3]), "r"(b0), "r"(b1));
}
__device__ __forceinline__ float fsig(float x)  { return __fdividef(1.f, 1.f + __expf(-x)); }
__device__ __forceinline__ float ftanh(float x) { return __fdividef(2.f, 1.f + __expf(-2.f * x)) - 1.f; }

// ---------------- setup ------------------------------------------------------
__global__ void w2h_kernel(const float* __restrict__ Wi, const float* __restrict__ Wg,
                           const float* __restrict__ Wo, const float* __restrict__ Wout) {
    int i = blockIdx.x * blockDim.x + threadIdx.x;
    if (i >= 4 * HID * HID) return;
    int m = i >> 18, r = i & (HID * HID - 1);
    const float* src = (m == 0) ? Wi : (m == 1) ? Wg : (m == 2) ? Wo : Wout;
    g_wh[m][r] = __float2half_rn(src[r]);
}

__global__ void copy_z_kernel(const float* __restrict__ y) {
    int i = blockIdx.x * blockDim.x + threadIdx.x;
    if (i < BATCH * HID) { float v = y[i]; g_z[i] = v; g_zh[i] = __float2half_rn(v); }
}

// ---------------- cp.async issuers (stage 0..2; 512 threads) -----------------
__device__ __forceinline__ void f_issue(uint32_t sb, int tid, int bm, int bn, int ch, int stage) {
    const uint32_t base = sb + (uint32_t)stage * F_STAGE_B;
    const int k0 = ch * BKE;
    #pragma unroll
    for (int i = 0; i < 8; ++i) {
        int idx = i * 512 + tid;              // 0..4095 segments of 16B
        int tl = idx >> 10, r = (idx >> 3) & 127, c = idx & 7;
        const __half* src = (tl == 0)
            ? (g_zh + (bm + r) * HID + k0 + c * 8)
            : (g_wh[tl - 1] + (bn + r) * HID + k0 + c * 8);
        uint32_t dst = base + (uint32_t)(tl * TILE_B + r * SKB + c * 16);
        CP16(dst, src);
    }
    CPC();
}
__device__ __forceinline__ void w_issue(uint32_t sb, int tid, int bm, int bn, int ch, int stage) {
    const uint32_t base = sb + (uint32_t)stage * W_STAGE_B;
    const int k0 = ch * BKE;
    #pragma unroll
    for (int i = 0; i < 4; ++i) {
        int idx = i * 512 + tid;              // 0..2047
        int tl = idx >> 10, r = (idx >> 3) & 127, c = idx & 7;
        const __half* src = (tl == 0)
            ? (g_dhh + (bm + r) * HID + k0 + c * 8)
            : (g_wh[3] + (bn + r) * HID + k0 + c * 8);
        uint32_t dst = base + (uint32_t)(tl * TILE_B + r * SKB + c * 16);
        CP16(dst, src);
    }
    CPC();
}

// ---------------- fused i/g/o HMMA GEMM (128x128 tile, 16 warps, f16 acc) ----
// dh = sig(z@Wo^T) * tanh( sig(z@Wi^T) * tanh(z@Wg^T) ) -> g_dhh (fp16)
__global__ __launch_bounds__(512, 1) void fused_igo_mma() {
    extern __shared__ __half sm[];
    const uint32_t sb = smem_u32(sm);
    const int tid = threadIdx.x, lane = tid & 31, wid = tid >> 5;
    const int warpM = wid & 3, warpN = wid >> 2;      // 4 x 4 warps, warp tile 32x32
    const int bm = blockIdx.x * BM, bn = blockIdx.y * BN;

    uint32_t acc[3][2][4][2];                         // [weight][mi][ni][2 half2-regs]
    #pragma unroll
    for (int w = 0; w < 3; ++w)
        #pragma unroll
        for (int mi = 0; mi < 2; ++mi)
            #pragma unroll
            for (int ni = 0; ni < 4; ++ni) { acc[w][mi][ni][0] = 0u; acc[w][mi][ni][1] = 0u; }

    const int am = warpM * 32 + (lane & 15);
    const int akb = (lane >> 4) << 4;                 // 0 or 16 bytes (8 fp16)
    const int brow0 = warpN * 32 + ((lane >> 4) << 3) + (lane & 7);
    const int bkb = ((lane >> 3) & 1) << 4;           // 0 or 16 bytes

    f_issue(sb, tid, bm, bn, 0, 0);
    f_issue(sb, tid, bm, bn, 1, 1);

    int stage = 0;
    #pragma unroll 1
    for (int ch = 0; ch < HID / BKE; ++ch) {
        if (ch < HID / BKE - 1) { CPW1(); } else { CPW0(); }
        __syncthreads();
        if (ch + 2 < HID / BKE) {
            int ns = stage + 2; if (ns >= 3) ns -= 3;
            f_issue(sb, tid, bm, bn, ch + 2, ns);
        }
        const uint32_t base = sb + (uint32_t)stage * F_STAGE_B;
        #pragma unroll
        for (int kk = 0; kk < BKE; kk += 16) {        // 4 k16 slices
            uint32_t fa[2][4];
            uint32_t aadr = base + (uint32_t)(am * SKB + kk * 2 + akb);
            ldm4(aadr,            fa[0][0], fa[0][1], fa[0][2], fa[0][3]);
            ldm4(aadr + 16 * SKB, fa[1][0], fa[1][1], fa[1][2], fa[1][3]);
            #pragma unroll
            for (int w = 0; w < 3; ++w) {
                const uint32_t wb = base + (uint32_t)((w + 1) * TILE_B) + (uint32_t)(kk * 2 + bkb);
                #pragma unroll
                for (int g = 0; g < 2; ++g) {
                    uint32_t b0, b1, b2, b3;
                    ldm4(wb + (uint32_t)((brow0 + g * 16) * SKB), b0, b1, b2, b3);
                    mma_f16(acc[w][0][2 * g + 0], fa[0], b0, b1);
                    mma_f16(acc[w][0][2 * g + 1], fa[0], b2, b3);
                    mma_f16(acc[w][1][2 * g + 0], fa[1], b0, b1);
                    mma_f16(acc[w][1][2 * g + 1], fa[1], b2, b3);
                }
            }
        }
        if (++stage >= 3) stage -= 3;
    }

    // epilogue: dh activation -> g_dhh (fp16)
    #pragma unroll
    for (int mi = 0; mi < 2; ++mi) {
        #pragma unroll
        for (int rr = 0; rr < 2; ++rr) {
            const int r = bm + warpM * 32 + mi * 16 + rr * 8 + (lane >> 2);
            #pragma unroll
            for (int ni = 0; ni < 4; ++ni) {
                const int col = bn + warpN * 32 + ni * 8 + ((lane & 3) << 1);
                float2 pi = __half22float2(*(__half2*)&acc[0][mi][ni][rr]);
                float2 pg = __half22float2(*(__half2*)&acc[1][mi][ni][rr]);
                float2 po = __half22float2(*(__half2*)&acc[2][mi][ni][rr]);
                float d0 = fsig(po.x) * ftanh(fsig(pi.x) * ftanh(pg.x));
                float d1 = fsig(po.y) * ftanh(fsig(pi.y) * ftanh(pg.y));
                *(__half2*)(g_dhh + r * HID + col) = __floats2half2_rn(d0, d1);
            }
        }
    }
}

// ---------------- Wout HMMA GEMM: s = dh @ Wout^T + bout (f16 acc) -----------
__global__ __launch_bounds__(512, 2) void wout_mma(const float* __restrict__ bout) {
    extern __shared__ __half sm[];
    const uint32_t sb = smem_u32(sm);
    const int tid = threadIdx.x, lane = tid & 31, wid = tid >> 5;
    const int warpM = wid & 3, warpN = wid >> 2;
    const int bm = blockIdx.x * BM, bn = blockIdx.y * BN;

    uint32_t acc[2][4][2];
    #pragma unroll
    for (int mi = 0; mi < 2; ++mi)
        #pragma unroll
        for (int ni = 0; ni < 4; ++ni) { acc[mi][ni][0] = 0u; acc[mi][ni][1] = 0u; }

    const int am = warpM * 32 + (lane & 15);
    const int akb = (lane >> 4) << 4;
    const int brow0 = warpN * 32 + ((lane >> 4) << 3) + (lane & 7);
    const int bkb = ((lane >> 3) & 1) << 4;

    w_issue(sb, tid, bm, bn, 0, 0);
    w_issue(sb, tid, bm, bn, 1, 1);

    int stage = 0;
    #pragma unroll 1
    for (int ch = 0; ch < HID / BKE; ++ch) {
        if (ch < HID / BKE - 1) { CPW1(); } else { CPW0(); }
        __syncthreads();
        if (ch + 2 < HID / BKE) {
            int ns = stage + 2; if (ns >= 3) ns -= 3;
            w_issue(sb, tid, bm, bn, ch + 2, ns);
        }
        const uint32_t base = sb + (uint32_t)stage * W_STAGE_B;
        #pragma unroll
        for (int kk = 0; kk < BKE; kk += 16) {
            uint32_t fa[2][4];
            uint32_t aadr = base + (uint32_t)(am * SKB + kk * 2 + akb);
            ldm4(aadr,            fa[0][0], fa[0][1], fa[0][2], fa[0][3]);
            ldm4(aadr + 16 * SKB, fa[1][0], fa[1][1], fa[1][2], fa[1][3]);
            const uint32_t wb = base + (uint32_t)TILE_B + (uint32_t)(kk * 2 + bkb);
            #pragma unroll
            for (int g = 0; g < 2; ++g) {
                uint32_t b0, b1, b2, b3;
                ldm4(wb + (uint32_t)((brow0 + g * 16) * SKB), b0, b1, b2, b3);
                mma_f16(acc[0][2 * g + 0], fa[0], b0, b1);
                mma_f16(acc[0][2 * g + 1], fa[0], b2, b3);
                mma_f16(acc[1][2 * g + 0], fa[1], b0, b1);
                mma_f16(acc[1][2 * g + 1], fa[1], b2, b3);
            }
        }
        if (++stage >= 3) stage -= 3;
    }

    #pragma unroll
    for (int mi = 0; mi < 2; ++mi) {
        #pragma unroll
        for (int rr = 0; rr < 2; ++rr) {
            const int r = bm + warpM * 32 + mi * 16 + rr * 8 + (lane >> 2);
            #pragma unroll
            for (int ni = 0; ni < 4; ++ni) {
                const int col = bn + warpN * 32 + ni * 8 + ((lane & 3) << 1);
                float2 v = __half22float2(*(__half2*)&acc[mi][ni][rr]);
                float2 o = { v.x + bout[col], v.y + bout[col + 1] };
                *(float2*)(g_s + r * HID + col) = o;
            }
        }
    }
}

// ---------------- fused softmax(s)->z update + softmax(z)->out[t+1] ----------
__global__ __launch_bounds__(256) void update_out_kernel(
    const float* __restrict__ ts, const float* __restrict__ Wfc,
    const float* __restrict__ bfc, float* __restrict__ out, int t)
{
    const int b = blockIdx.x;
    const int tid = threadIdx.x;
    __shared__ float red_a[8], red_b[8];

    float v0 = g_s[b * HID + tid], v1 = g_s[b * HID + tid + 256];
    float m = fmaxf(v0, v1);
    #pragma unroll
    for (int o = 16; o; o >>= 1) m = fmaxf(m, __shfl_xor_sync(0xffffffffu, m, o));
    if ((tid & 31) == 0) red_a[tid >> 5] = m;
    __syncthreads();
    if (tid == 0) {
        float mm = red_a[0];
        #pragma unroll
        for (int i = 1; i < 8; ++i) mm = fmaxf(mm, red_a[i]);
        red_a[0] = mm;
    }
    __syncthreads();
    m = red_a[0];
    __syncthreads();
    float e0 = __expf(v0 - m), e1 = __expf(v1 - m);
    float s = e0 + e1;
    #pragma unroll
    for (int o = 16; o; o >>= 1) s += __shfl_xor_sync(0xffffffffu, s, o);
    if ((tid & 31) == 0) red_a[tid >> 5] = s;
    __syncthreads();
    if (tid == 0) {
        float ss = 0.f;
        #pragma unroll
        for (int i = 0; i < 8; ++i) ss += red_a[i];
        red_a[0] = ss;
    }
    __syncthreads();
    float dt = ts[t + 1] - ts[t];
    float inv = __fdividef(dt, red_a[0]);
    float z0 = g_z[b * HID + tid      ] + e0 * inv;
    float z1 = g_z[b * HID + tid + 256] + e1 * inv;
    g_z[b * HID + tid      ] = z0;
    g_z[b * HID + tid + 256] = z1;
    g_zh[b * HID + tid      ] = __float2half_rn(z0);
    g_zh[b * HID + tid + 256] = __float2half_rn(z1);
    __syncthreads();

    m = fmaxf(z0, z1);
    #pragma unroll
    for (int o = 16; o; o >>= 1) m = fmaxf(m, __shfl_xor_sync(0xffffffffu, m, o));
    if ((tid & 31) == 0) red_a[tid >> 5] = m;
    __syncthreads();
    if (tid == 0) {
        float mm = red_a[0];
        #pragma unroll
        for (int i = 1; i < 8; ++i) mm = fmaxf(mm, red_a[i]);
        red_a[0] = mm;
    }
    __syncthreads();
    m = red_a[0];
    __syncthreads();
    e0 = __expf(z0 - m); e1 = __expf(z1 - m);
    s = e0 + e1;
    float d = e0 * Wfc[tid] + e1 * Wfc[tid + 256];
    #pragma unroll
    for (int o = 16; o; o >>= 1) {
        s += __shfl_xor_sync(0xffffffffu, s, o);
        d += __shfl_xor_sync(0xffffffffu, d, o);
    }
    if ((tid & 31) == 0) { red_a[tid >> 5] = s; red_b[tid >> 5] = d; }
    __syncthreads();
    if (tid == 0) {
        float ss = 0.f, dd = 0.f;
        #pragma unroll
        for (int i = 0; i < 8; ++i) { ss += red_a[i]; dd += red_b[i]; }
        out[b * TSTEPS + t + 1] = __fdividef(dd, ss) + bfc[0];
    }
}

// out[b, 0] = softmax_row(z[b]) . Wfc + bfc
__global__ __launch_bounds__(256) void softmaxdot_kernel(
    const float* __restrict__ Wfc, const float* __restrict__ bfc,
    float* __restrict__ out)
{
    const int b = blockIdx.x;
    const int tid = threadIdx.x;
    float v0 = g_z[b * HID + tid], v1 = g_z[b * HID + tid + 256];
    __shared__ float red_s[8], red_d[8];

    float m = fmaxf(v0, v1);
    #pragma unroll
    for (int o = 16; o; o >>= 1) m = fmaxf(m, __shfl_xor_sync(0xffffffffu, m, o));
    if ((tid & 31) == 0) red_s[tid >> 5] = m;
    __syncthreads();
    if (tid == 0) {
        float mm = red_s[0];
        #pragma unroll
        for (int i = 1; i < 8; ++i) mm = fmaxf(mm, red_s[i]);
        red_s[0] = mm;
    }
    __syncthreads();
    m = red_s[0];
    __syncthreads();
    float e0 = __expf(v0 - m), e1 = __expf(v1 - m);
    float s = e0 + e1;
    float d = e0 * Wfc[tid] + e1 * Wfc[tid + 256];
    #pragma unroll
    for (int o = 16; o; o >>= 1) {
        s += __shfl_xor_sync(0xffffffffu, s, o);
        d += __shfl_xor_sync(0xffffffffu, d, o);
    }
    if ((tid & 31) == 0) { red_s[tid >> 5] = s; red_d[tid >> 5] = d; }
    __syncthreads();
    if (tid == 0) {
        float ss = 0.f, dd = 0.f;
        #pragma unroll
        for (int i = 0; i < 8; ++i) { ss += red_s[i]; dd += red_d[i]; }
        out[b * TSTEPS + 0] = __fdividef(dd, ss) + bfc[0];
    }
}

// ---------------- launch -----------------------------------------------------
extern "C" void kernel_launch(void* const* d_in, const int* in_sizes, int n_in,
                              void* d_out, int out_size) {
    const float* y    = (const float*)d_in[0];
    const float* ts   = (const float*)d_in[1];
    const float* Wi   = (const float*)d_in[2];
    // d_in[3] = Wf — dead in the reference (f computed but unused), skipped.
    const float* Wg   = (const float*)d_in[4];
    const float* Wo   = (const float*)d_in[5];
    const float* Wout = (const float*)d_in[6];
    const float* bout = (const float*)d_in[7];
    const float* Wfc  = (const float*)d_in[8];
    const float* bfc  = (const float*)d_in[9];
    float* out = (float*)d_out;

    cudaFuncSetAttribute(fused_igo_mma, cudaFuncAttributeMaxDynamicSharedMemorySize, F_SMEM);
    cudaFuncSetAttribute(wout_mma,      cudaFuncAttributeMaxDynamicSharedMemorySize, W_SMEM);

    w2h_kernel<<<(4 * HID * HID + 255) / 256, 256>>>(Wi, Wg, Wo, Wout);
    copy_z_kernel<<<(BATCH * HID + 255) / 256, 256>>>(y);
    softmaxdot_kernel<<<BATCH, 256>>>(Wfc, bfc, out);

    dim3 ggrid(BATCH / BM, HID / BN);   // 32 x 4 = 128 CTAs
    for (int t = 0; t < TSTEPS - 1; ++t) {
        fused_igo_mma<<<ggrid, 512, F_SMEM>>>();
        wout_mma<<<ggrid, 512, W_SMEM>>>(bout);
        update_out_kernel<<<BATCH, 256>>>(ts, Wfc, bfc, out, t);
    }
}